// round 3
// baseline (speedup 1.0000x reference)
#include <cuda_runtime.h>
#include <cuda_bf16.h>

typedef unsigned long long ull;

#define PIDX(k,b) (((((k)>>1))<<6) + (((b))<<1) + ((k)&1))

// ---------------- device scratch ----------------
__device__ __align__(16) float g_xn [512*1024*32]; // xn packed  [t][d2][b][2]
__device__ __align__(16) float g_cx [512*1024*32]; // cfc_x packed
__device__ __align__(16) float g_co [512*1024*32]; // cfc_out packed
__device__ __align__(16) float g_h  [1024*32];     // hidden packed
__device__ __align__(16) float g_b1 [2048*32];     // backbone L0 out packed
__device__ __align__(16) float g_b2 [2048*32];     // backbone L1 out packed
__device__ __align__(16) float g_hd [4096*32];     // heads raw packed
__device__ __align__(16) float g_winT [1024*1024]; // [j][k]
__device__ __align__(16) float g_w0T  [2048*2048];
__device__ __align__(16) float g_w1T  [2048*2048];
__device__ __align__(16) float g_whT  [4096*2048]; // ff1|ff2|ta|tb rows
__device__ __align__(16) float g_woutT[1024*1024];
__device__ unsigned g_bar;

// ---------------- helpers ----------------
__device__ __forceinline__ ull f2fma(ull a, ull b, ull c) {
    ull d; asm("fma.rn.f32x2 %0,%1,%2,%3;" : "=l"(d) : "l"(a), "l"(b), "l"(c));
    return d;
}
__device__ __forceinline__ float2 u2f(ull v) {
    float2 f; asm("mov.b64 {%0,%1},%2;" : "=f"(f.x), "=f"(f.y) : "l"(v));
    return f;
}

__global__ void k_init() { g_bar = 0u; }

__device__ __forceinline__ void gridbar(unsigned& gen) {
    __syncthreads();
    if (threadIdx.x == 0) {
        gen++;
        unsigned tgt = gen * gridDim.x;
        __threadfence();
        atomicAdd(&g_bar, 1u);
        unsigned v;
        do {
            asm volatile("ld.acquire.gpu.u32 %0,[%1];" : "=r"(v) : "l"(&g_bar) : "memory");
        } while (v < tgt);
    }
    __syncthreads();
}

// ---------------- transpose out[c][r]=in[r][c] ----------------
__global__ __launch_bounds__(256) void k_tr(const float* __restrict__ in,
                                            float* __restrict__ out, int R, int C) {
    __shared__ float tile[32][33];
    int c0 = blockIdx.x * 32, r0 = blockIdx.y * 32;
    int x = threadIdx.x, y = threadIdx.y;
#pragma unroll
    for (int i = 0; i < 32; i += 8)
        tile[y + i][x] = in[(size_t)(r0 + y + i) * C + c0 + x];
    __syncthreads();
#pragma unroll
    for (int i = 0; i < 32; i += 8)
        out[(size_t)(c0 + y + i) * R + r0 + x] = tile[x][y + i];
}

// ---------------- layernorm -> packed xn ----------------
__global__ __launch_bounds__(256) void k_ln(const float* __restrict__ x,
                                            const float* __restrict__ nw,
                                            const float* __restrict__ nb) {
    const int t = blockIdx.x;
    __shared__ float smu[32], srs[32];
    int warp = threadIdx.x >> 5, lane = threadIdx.x & 31;
    for (int b = warp; b < 32; b += 8) {
        const float* row = x + (size_t)b * 524288 + (size_t)t * 1024;
        float s = 0.f, s2 = 0.f;
        for (int d = lane; d < 1024; d += 32) { float v = row[d]; s += v; s2 += v * v; }
#pragma unroll
        for (int o = 16; o; o >>= 1) {
            s  += __shfl_xor_sync(0xffffffffu, s, o);
            s2 += __shfl_xor_sync(0xffffffffu, s2, o);
        }
        if (lane == 0) {
            float mu = s * (1.f / 1024.f);
            float var = s2 * (1.f / 1024.f) - mu * mu;
            smu[b] = mu; srs[b] = rsqrtf(var + 1e-5f);
        }
    }
    __syncthreads();
    float* dst = g_xn + (size_t)t * 32768;
    for (int b = warp; b < 32; b += 8) {
        const float* row = x + (size_t)b * 524288 + (size_t)t * 1024;
        float mu = smu[b], rs = srs[b];
        for (int d = lane; d < 1024; d += 32)
            dst[PIDX(d, b)] = (row[d] - mu) * rs * nw[d] + nb[d];
    }
}

// ---------------- input projection: cfc_x = xn @ w_inT + b_in ----------------
__global__ __launch_bounds__(256) void k_gin(const float* __restrict__ bias) {
    const int tid = threadIdx.x, warp = tid >> 5, lane = tid & 31;
    const int j0 = blockIdx.x * 64 + warp * 8;
    const int t0 = blockIdx.y * 4;
    ull acc[4][8];
#pragma unroll
    for (int tt = 0; tt < 4; tt++)
#pragma unroll
        for (int j = 0; j < 8; j++) acc[tt][j] = 0ull;
    const ull* xp = (const ull*)g_xn;
#pragma unroll 1
    for (int k4 = 0; k4 < 256; k4++) {
        ull a0[4], a1[4];
#pragma unroll
        for (int tt = 0; tt < 4; tt++) {
            const ull* ap = xp + (size_t)(t0 + tt) * 16384 + (size_t)(2 * k4) * 32;
            a0[tt] = ap[lane]; a1[tt] = ap[lane + 32];
        }
#pragma unroll
        for (int j = 0; j < 8; j++) {
            ulonglong2 wv = *(const ulonglong2*)(g_winT + (size_t)(j0 + j) * 1024 + 4 * k4);
#pragma unroll
            for (int tt = 0; tt < 4; tt++) {
                acc[tt][j] = f2fma(a0[tt], wv.x, acc[tt][j]);
                acc[tt][j] = f2fma(a1[tt], wv.y, acc[tt][j]);
            }
        }
    }
#pragma unroll
    for (int tt = 0; tt < 4; tt++)
#pragma unroll
        for (int j = 0; j < 8; j++) {
            float2 s = u2f(acc[tt][j]);
            g_cx[(size_t)(t0 + tt) * 32768 + PIDX(j0 + j, lane)] = s.x + s.y + bias[j0 + j];
        }
}

// ---------------- output projection + residual ----------------
__global__ __launch_bounds__(256) void k_gout(const float* __restrict__ bias,
                                              const float* __restrict__ x,
                                              float* __restrict__ y) {
    const int tid = threadIdx.x, warp = tid >> 5, lane = tid & 31;
    const int j0 = blockIdx.x * 64 + warp * 8;
    const int t0 = blockIdx.y * 4;
    ull acc[4][8];
#pragma unroll
    for (int tt = 0; tt < 4; tt++)
#pragma unroll
        for (int j = 0; j < 8; j++) acc[tt][j] = 0ull;
    const ull* cp = (const ull*)g_co;
#pragma unroll 1
    for (int k4 = 0; k4 < 256; k4++) {
        ull a0[4], a1[4];
#pragma unroll
        for (int tt = 0; tt < 4; tt++) {
            const ull* ap = cp + (size_t)(t0 + tt) * 16384 + (size_t)(2 * k4) * 32;
            a0[tt] = ap[lane]; a1[tt] = ap[lane + 32];
        }
#pragma unroll
        for (int j = 0; j < 8; j++) {
            ulonglong2 wv = *(const ulonglong2*)(g_woutT + (size_t)(j0 + j) * 1024 + 4 * k4);
#pragma unroll
            for (int tt = 0; tt < 4; tt++) {
                acc[tt][j] = f2fma(a0[tt], wv.x, acc[tt][j]);
                acc[tt][j] = f2fma(a1[tt], wv.y, acc[tt][j]);
            }
        }
    }
#pragma unroll
    for (int tt = 0; tt < 4; tt++)
#pragma unroll
        for (int j = 0; j < 8; j++) {
            int d = j0 + j;
            size_t oi = (size_t)lane * 524288 + (size_t)(t0 + tt) * 1024 + d;
            float2 s = u2f(acc[tt][j]);
            y[oi] = s.x + s.y + bias[d] + x[oi];
        }
}

// ---------------- scan GEMM phase: block computes 16 j rows, k-split by warp --
__device__ __forceinline__ void phase16(const ull* __restrict__ actA,
                                        const ull* __restrict__ actB, int splitK2,
                                        const float* __restrict__ wrow,
                                        float2* __restrict__ sred, int warp, int lane) {
    ull acc[16];
#pragma unroll
    for (int j = 0; j < 16; j++) acc[j] = 0ull;
    const int k2lo = warp * 128;
#pragma unroll 1
    for (int k2 = k2lo; k2 < k2lo + 128; k2 += 2) {
        const ull* ap = (k2 < splitK2) ? (actA + (size_t)k2 * 32)
                                       : (actB + (size_t)(k2 - splitK2) * 32);
        ull a0 = ap[lane];
        ull a1 = ap[lane + 32];
        const float* wb = wrow + 2 * k2;
#pragma unroll
        for (int j = 0; j < 16; j++) {
            ulonglong2 wv = *(const ulonglong2*)(wb + (size_t)j * 2048);
            acc[j] = f2fma(a0, wv.x, acc[j]);
            acc[j] = f2fma(a1, wv.y, acc[j]);
        }
    }
#pragma unroll
    for (int j = 0; j < 16; j++) sred[(warp * 16 + j) * 32 + lane] = u2f(acc[j]);
}

__device__ __forceinline__ float redsum(const float2* __restrict__ sred, int jj, int lane) {
    float sx = 0.f, sy = 0.f;
#pragma unroll
    for (int w = 0; w < 8; w++) {
        float2 v = sred[(w * 16 + jj) * 32 + lane];
        sx += v.x; sy += v.y;
    }
    return sx + sy;
}

// ---------------- persistent CfC scan ----------------
__global__ __launch_bounds__(256) void k_scan(const float* __restrict__ tsp,
                                              const float* __restrict__ hid,
                                              const float* __restrict__ bbb,
                                              const float* __restrict__ bf1,
                                              const float* __restrict__ bf2,
                                              const float* __restrict__ bta,
                                              const float* __restrict__ btb) {
    __shared__ float2 sred[4096];
    const int tid = threadIdx.x, warp = tid >> 5, lane = tid & 31, bid = blockIdx.x;
    unsigned gen = 0;
    {   // init hidden (32768 threads, one element each)
        int i = bid * 256 + tid;
        int u = i >> 5, b = i & 31;
        g_h[PIDX(u, b)] = hid[b * 1024 + u];
    }
    gridbar(gen);
    const int j0 = bid * 16;
    for (int t = 0; t < 512; t++) {
        const ull* cxp = (const ull*)g_cx + (size_t)t * 16384;
        // backbone layer 0 (act = concat[cfc_x_t, h])
        phase16(cxp, (const ull*)g_h, 512, g_w0T + (size_t)j0 * 2048, sred, warp, lane);
        __syncthreads();
        for (int jj = warp; jj < 16; jj += 8) {
            float v = redsum(sred, jj, lane) + bbb[j0 + jj];
            g_b1[PIDX(j0 + jj, lane)] = 1.7159f * tanhf(0.666f * v);
        }
        gridbar(gen);
        // backbone layer 1
        phase16((const ull*)g_b1, (const ull*)g_b1, 4096, g_w1T + (size_t)j0 * 2048, sred, warp, lane);
        __syncthreads();
        for (int jj = warp; jj < 16; jj += 8) {
            float v = redsum(sred, jj, lane) + bbb[2048 + j0 + jj];
            g_b2[PIDX(j0 + jj, lane)] = 1.7159f * tanhf(0.666f * v);
        }
        gridbar(gen);
        // heads (ff1|ff2|ta|tb), two chunks of 2048 outputs
#pragma unroll 1
        for (int c = 0; c < 2; c++) {
            if (c) __syncthreads();
            phase16((const ull*)g_b2, (const ull*)g_b2, 4096,
                    g_whT + (size_t)(c * 2048 + j0) * 2048, sred, warp, lane);
            __syncthreads();
            for (int jj = warp; jj < 16; jj += 8) {
                int jp = c * 2048 + j0 + jj;
                int hs = jp >> 10;
                const float* bp = (hs == 0) ? bf1 : (hs == 1) ? bf2 : (hs == 2) ? bta : btb;
                g_hd[PIDX(jp, lane)] = redsum(sred, jj, lane) + bp[jp & 1023];
            }
        }
        gridbar(gen);
        // elementwise CfC gate
        {
            int i = bid * 256 + tid;
            int u = i >> 5, b = i & 31;
            float f1 = tanhf(g_hd[PIDX(u, b)]);
            float f2 = tanhf(g_hd[PIDX(1024 + u, b)]);
            float ta = g_hd[PIDX(2048 + u, b)];
            float tb = g_hd[PIDX(3072 + u, b)];
            float ts = tsp[b * 512 + t];
            float ti = 1.f / (1.f + expf(-(ta * ts + tb)));
            float hn = f1 - ti * f1 + ti * f2;
            int p = PIDX(u, b);
            g_h[p] = hn;
            g_co[(size_t)t * 32768 + p] = hn;
        }
        gridbar(gen);
    }
}

// ---------------- h_final writeback ----------------
__global__ void k_hf(float* __restrict__ out) {
    int i = blockIdx.x * 256 + threadIdx.x;
    int u = i & 1023, b = i >> 10;
    out[i] = g_h[PIDX(u, b)];
}

// ---------------- host ----------------
extern "C" void kernel_launch(void* const* d_in, const int* in_sizes, int n_in,
                              void* d_out, int out_size) {
    const float* x    = (const float*)d_in[0];
    const float* tsp  = (const float*)d_in[1];
    const float* hid  = (const float*)d_in[2];
    const float* nw   = (const float*)d_in[3];
    const float* nb   = (const float*)d_in[4];
    const float* w_in = (const float*)d_in[5];
    const float* b_in = (const float*)d_in[6];
    const float* bbw  = (const float*)d_in[7];
    const float* bbb  = (const float*)d_in[8];
    const float* wf1  = (const float*)d_in[9];
    const float* bf1  = (const float*)d_in[10];
    const float* wf2  = (const float*)d_in[11];
    const float* bf2  = (const float*)d_in[12];
    const float* wta  = (const float*)d_in[13];
    const float* bta  = (const float*)d_in[14];
    const float* wtb  = (const float*)d_in[15];
    const float* btb  = (const float*)d_in[16];
    const float* w_out= (const float*)d_in[17];
    const float* b_out= (const float*)d_in[18];
    float* y  = (float*)d_out;
    float* hf = y + 16777216;

    float *winT, *w0T, *w1T, *whT, *woutT;
    cudaGetSymbolAddress((void**)&winT,  g_winT);
    cudaGetSymbolAddress((void**)&w0T,   g_w0T);
    cudaGetSymbolAddress((void**)&w1T,   g_w1T);
    cudaGetSymbolAddress((void**)&whT,   g_whT);
    cudaGetSymbolAddress((void**)&woutT, g_woutT);

    dim3 tb(32, 8);
    k_init<<<1, 1>>>();
    k_tr<<<dim3(32, 32), tb>>>(w_in, winT, 1024, 1024);
    k_tr<<<dim3(64, 64), tb>>>(bbw,            w0T, 2048, 2048);
    k_tr<<<dim3(64, 64), tb>>>(bbw + 4194304,  w1T, 2048, 2048);
    k_tr<<<dim3(32, 64), tb>>>(wf1, whT,           2048, 1024);
    k_tr<<<dim3(32, 64), tb>>>(wf2, whT + 2097152, 2048, 1024);
    k_tr<<<dim3(32, 64), tb>>>(wta, whT + 4194304, 2048, 1024);
    k_tr<<<dim3(32, 64), tb>>>(wtb, whT + 6291456, 2048, 1024);
    k_tr<<<dim3(32, 32), tb>>>(w_out, woutT, 1024, 1024);
    k_ln<<<512, 256>>>(x, nw, nb);
    k_gin<<<dim3(16, 128), 256>>>(b_in);
    k_scan<<<128, 256>>>(tsp, hid, bbb, bf1, bf2, bta, btb);
    k_gout<<<dim3(16, 128), 256>>>(b_out, x, y);
    k_hf<<<128, 256>>>(hf);
}

// round 4
// speedup vs baseline: 2.0752x; 2.0752x over previous
#include <cuda_runtime.h>
#include <cstdint>

typedef unsigned long long ull;

#define PIDX(k,b) (((((k)>>1))<<6) + (((b))<<1) + ((k)&1))

// ---------------- device scratch ----------------
__device__ __align__(16) float g_xn [512*1024*32]; // xn packed  [t][d2][b][2]
__device__ __align__(16) float g_cx [512*1024*32]; // cfc_x packed
__device__ __align__(16) float g_co [512*1024*32]; // cfc_out packed
__device__ __align__(16) float g_h  [1024*32];     // hidden packed
__device__ __align__(16) float g_b1 [2048*32];     // backbone L0 out packed
__device__ __align__(16) float g_b2 [2048*32];     // backbone L1 out packed
__device__ __align__(16) float g_winT [1024*1024]; // [j][k]
__device__ __align__(16) float g_w0T  [2048*2048];
__device__ __align__(16) float g_w1T  [2048*2048];
__device__ __align__(16) float g_whT  [4096*2048]; // interleaved heads rows
__device__ __align__(16) float g_woutT[1024*1024];
__device__ unsigned g_bar;

// ---------------- helpers ----------------
__device__ __forceinline__ ull f2fma(ull a, ull b, ull c) {
    ull d; asm("fma.rn.f32x2 %0,%1,%2,%3;" : "=l"(d) : "l"(a), "l"(b), "l"(c));
    return d;
}
__device__ __forceinline__ float2 u2f(ull v) {
    float2 f; asm("mov.b64 {%0,%1},%2;" : "=f"(f.x), "=f"(f.y) : "l"(v));
    return f;
}
__device__ __forceinline__ void cpa16(uint32_t s, const float* g) {
    asm volatile("cp.async.cg.shared.global [%0],[%1],16;" :: "r"(s), "l"(g));
}
__device__ __forceinline__ void cp_commit() { asm volatile("cp.async.commit_group;"); }

__global__ void k_init() { g_bar = 0u; }

__device__ __forceinline__ void gridbar(unsigned& gen) {
    __syncthreads();
    if (threadIdx.x == 0) {
        gen++;
        unsigned tgt = gen * gridDim.x;
        __threadfence();
        atomicAdd(&g_bar, 1u);
        unsigned v;
        do {
            asm volatile("ld.acquire.gpu.u32 %0,[%1];" : "=r"(v) : "l"(&g_bar) : "memory");
        } while (v < tgt);
    }
    __syncthreads();
}

// ---------------- fused transposes ----------------
// A: backbone weights w0T, w1T (2048x2048 each), z selects layer
__global__ __launch_bounds__(256) void k_trA(const float* __restrict__ bbw) {
    __shared__ float tile[32][33];
    const float* src = bbw + (size_t)blockIdx.z * 4194304;
    float* dst = blockIdx.z ? g_w1T : g_w0T;
    int c0 = blockIdx.x * 32, r0 = blockIdx.y * 32;
    int x = threadIdx.x, y = threadIdx.y;
#pragma unroll
    for (int i = 0; i < 32; i += 8)
        tile[y + i][x] = src[(size_t)(r0 + y + i) * 2048 + c0 + x];
    __syncthreads();
#pragma unroll
    for (int i = 0; i < 32; i += 8)
        dst[(size_t)(c0 + y + i) * 2048 + r0 + x] = tile[x][y + i];
}

// B: win (z=0), wout (z=1), heads h=z-2 with interleaved row mapping
__global__ __launch_bounds__(256) void k_trB(const float* __restrict__ win,
                                             const float* __restrict__ wout,
                                             const float* __restrict__ wf1,
                                             const float* __restrict__ wf2,
                                             const float* __restrict__ wta,
                                             const float* __restrict__ wtb) {
    __shared__ float tile[32][33];
    int z = blockIdx.z;
    int c0 = blockIdx.x * 32, r0 = blockIdx.y * 32;
    int x = threadIdx.x, y = threadIdx.y;
    if (z < 2) {
        if (blockIdx.y >= 32) return;
        const float* src = z ? wout : win;
        float* dst = z ? g_woutT : g_winT;
#pragma unroll
        for (int i = 0; i < 32; i += 8)
            tile[y + i][x] = src[(size_t)(r0 + y + i) * 1024 + c0 + x];
        __syncthreads();
#pragma unroll
        for (int i = 0; i < 32; i += 8)
            dst[(size_t)(c0 + y + i) * 1024 + r0 + x] = tile[x][y + i];
    } else {
        int h = z - 2;
        const float* src = h == 0 ? wf1 : h == 1 ? wf2 : h == 2 ? wta : wtb;
        // src [2048 k][1024 j]; dst row = (j>>3)*32 + h*8 + (j&7), ld 2048
#pragma unroll
        for (int i = 0; i < 32; i += 8)
            tile[y + i][x] = src[(size_t)(r0 + y + i) * 1024 + c0 + x];
        __syncthreads();
#pragma unroll
        for (int i = 0; i < 32; i += 8) {
            int j = c0 + y + i;
            int f = ((j >> 3) << 5) + h * 8 + (j & 7);
            g_whT[(size_t)f * 2048 + r0 + x] = tile[x][y + i];
        }
    }
}

// ---------------- layernorm -> packed xn ----------------
__global__ __launch_bounds__(256) void k_ln(const float* __restrict__ x,
                                            const float* __restrict__ nw,
                                            const float* __restrict__ nb) {
    const int t = blockIdx.x;
    __shared__ float smu[32], srs[32];
    int warp = threadIdx.x >> 5, lane = threadIdx.x & 31;
    for (int b = warp; b < 32; b += 8) {
        const float* row = x + (size_t)b * 524288 + (size_t)t * 1024;
        float s = 0.f, s2 = 0.f;
        for (int d = lane; d < 1024; d += 32) { float v = row[d]; s += v; s2 += v * v; }
#pragma unroll
        for (int o = 16; o; o >>= 1) {
            s  += __shfl_xor_sync(0xffffffffu, s, o);
            s2 += __shfl_xor_sync(0xffffffffu, s2, o);
        }
        if (lane == 0) {
            float mu = s * (1.f / 1024.f);
            float var = s2 * (1.f / 1024.f) - mu * mu;
            smu[b] = mu; srs[b] = rsqrtf(var + 1e-5f);
        }
    }
    __syncthreads();
    float* dst = g_xn + (size_t)t * 32768;
    for (int b = warp; b < 32; b += 8) {
        const float* row = x + (size_t)b * 524288 + (size_t)t * 1024;
        float mu = smu[b], rs = srs[b];
        for (int d = lane; d < 1024; d += 32)
            dst[PIDX(d, b)] = (row[d] - mu) * rs * nw[d] + nb[d];
    }
}

// ---------------- input projection: cfc_x = xn @ w_inT + b_in ----------------
__global__ __launch_bounds__(256) void k_gin(const float* __restrict__ bias) {
    const int tid = threadIdx.x, warp = tid >> 5, lane = tid & 31;
    const int j0 = blockIdx.x * 64 + warp * 8;
    const int t0 = blockIdx.y * 4;
    ull acc[4][8];
#pragma unroll
    for (int tt = 0; tt < 4; tt++)
#pragma unroll
        for (int j = 0; j < 8; j++) acc[tt][j] = 0ull;
    const ull* xp = (const ull*)g_xn;
#pragma unroll 1
    for (int k4 = 0; k4 < 256; k4++) {
        ull a0[4], a1[4];
#pragma unroll
        for (int tt = 0; tt < 4; tt++) {
            const ull* ap = xp + (size_t)(t0 + tt) * 16384 + (size_t)(2 * k4) * 32;
            a0[tt] = ap[lane]; a1[tt] = ap[lane + 32];
        }
#pragma unroll
        for (int j = 0; j < 8; j++) {
            ulonglong2 wv = *(const ulonglong2*)(g_winT + (size_t)(j0 + j) * 1024 + 4 * k4);
#pragma unroll
            for (int tt = 0; tt < 4; tt++) {
                acc[tt][j] = f2fma(a0[tt], wv.x, acc[tt][j]);
                acc[tt][j] = f2fma(a1[tt], wv.y, acc[tt][j]);
            }
        }
    }
#pragma unroll
    for (int tt = 0; tt < 4; tt++)
#pragma unroll
        for (int j = 0; j < 8; j++) {
            float2 s = u2f(acc[tt][j]);
            g_cx[(size_t)(t0 + tt) * 32768 + PIDX(j0 + j, lane)] = s.x + s.y + bias[j0 + j];
        }
}

// ---------------- output projection + residual ----------------
__global__ __launch_bounds__(256) void k_gout(const float* __restrict__ bias,
                                              const float* __restrict__ x,
                                              float* __restrict__ y) {
    const int tid = threadIdx.x, warp = tid >> 5, lane = tid & 31;
    const int j0 = blockIdx.x * 64 + warp * 8;
    const int t0 = blockIdx.y * 4;
    ull acc[4][8];
#pragma unroll
    for (int tt = 0; tt < 4; tt++)
#pragma unroll
        for (int j = 0; j < 8; j++) acc[tt][j] = 0ull;
    const ull* cp = (const ull*)g_co;
#pragma unroll 1
    for (int k4 = 0; k4 < 256; k4++) {
        ull a0[4], a1[4];
#pragma unroll
        for (int tt = 0; tt < 4; tt++) {
            const ull* ap = cp + (size_t)(t0 + tt) * 16384 + (size_t)(2 * k4) * 32;
            a0[tt] = ap[lane]; a1[tt] = ap[lane + 32];
        }
#pragma unroll
        for (int j = 0; j < 8; j++) {
            ulonglong2 wv = *(const ulonglong2*)(g_woutT + (size_t)(j0 + j) * 1024 + 4 * k4);
#pragma unroll
            for (int tt = 0; tt < 4; tt++) {
                acc[tt][j] = f2fma(a0[tt], wv.x, acc[tt][j]);
                acc[tt][j] = f2fma(a1[tt], wv.y, acc[tt][j]);
            }
        }
    }
#pragma unroll
    for (int tt = 0; tt < 4; tt++)
#pragma unroll
        for (int j = 0; j < 8; j++) {
            int d = j0 + j;
            size_t oi = (size_t)lane * 524288 + (size_t)(t0 + tt) * 1024 + d;
            float2 s = u2f(acc[tt][j]);
            y[oi] = s.x + s.y + bias[d] + x[oi];
        }
}

// ---------------- scan GEMM phase (smem staged, cp.async double-buffered) ----
// k-tile = 256 (128 k2-pairs, act tile 32KB). 8 tiles cover k=2048.
// Each warp handles a 16-k2 slice of each tile, accumulates ROWS outputs.
template<int ROWS>
__device__ __forceinline__ void prefetch_tile(float* sW, float* sA,
        const float* Wt, const float* At, int tid) {
    uint32_t sw = (uint32_t)__cvta_generic_to_shared(sW);
    uint32_t sa = (uint32_t)__cvta_generic_to_shared(sA);
#pragma unroll
    for (int r = 0; r < ROWS / 4; r++) {
        int o = r * 256 + tid;
        int row = o >> 6, c = (o & 63) << 2;
        cpa16(sw + (uint32_t)(row * 256 + c) * 4u, Wt + (size_t)row * 2048 + c);
    }
#pragma unroll
    for (int r = 0; r < 8; r++) {
        int o = r * 256 + tid;
        cpa16(sa + (uint32_t)o * 16u, At + o * 4);
    }
}

template<int ROWS>
__device__ __forceinline__ void gemm_phase(
    float* smem, const float* Wbase, const float* actA, const float* actB,
    int warp, int lane, int tid)
{
    float* sW0 = smem;          float* sW1 = smem + 8192;
    float* sA0 = smem + 16384;  float* sA1 = smem + 24576;
    float* sred = smem + 32768;
    ull acc[ROWS];
#pragma unroll
    for (int j = 0; j < ROWS; j++) acc[j] = 0ull;
    prefetch_tile<ROWS>(sW0, sA0, Wbase, actA, tid);
    cp_commit();
#pragma unroll 1
    for (int kt = 0; kt < 8; kt++) {
        if (kt < 7) {
            int n = kt + 1;
            const float* At = (n < 4) ? actA + n * 8192 : actB + (n - 4) * 8192;
            prefetch_tile<ROWS>((n & 1) ? sW1 : sW0, (n & 1) ? sA1 : sA0,
                                Wbase + n * 256, At, tid);
            cp_commit();
            asm volatile("cp.async.wait_group 1;");
        } else {
            asm volatile("cp.async.wait_group 0;");
        }
        __syncthreads();
        const float* w = (kt & 1) ? sW1 : sW0;
        const ull* au = (const ull*)((kt & 1) ? sA1 : sA0);
        const int k2lo = warp * 16;
#pragma unroll 2
        for (int k2 = 0; k2 < 16; k2 += 2) {
            ull a0 = au[(k2lo + k2) * 32 + lane];
            ull a1 = au[(k2lo + k2 + 1) * 32 + lane];
#pragma unroll
            for (int j = 0; j < ROWS; j++) {
                ulonglong2 wv = *(const ulonglong2*)(w + j * 256 + (k2lo + k2) * 2);
                acc[j] = f2fma(a0, wv.x, acc[j]);
                acc[j] = f2fma(a1, wv.y, acc[j]);
            }
        }
        __syncthreads();
    }
#pragma unroll
    for (int j = 0; j < ROWS; j++) {
        float2 p = u2f(acc[j]);
        sred[(warp * ROWS + j) * 32 + lane] = p.x + p.y;
    }
    __syncthreads();
}

// ---------------- persistent CfC scan ----------------
extern __shared__ float s_dyn[];

__global__ __launch_bounds__(256, 1) void k_scan(const float* __restrict__ tsp,
                                                 const float* __restrict__ hid,
                                                 const float* __restrict__ bbb,
                                                 const float* __restrict__ bf1,
                                                 const float* __restrict__ bf2,
                                                 const float* __restrict__ bta,
                                                 const float* __restrict__ btb) {
    float* smem = s_dyn;
    float* sred = smem + 32768;
    float* sH   = smem + 40960;
    const int tid = threadIdx.x, warp = tid >> 5, lane = tid & 31, bid = blockIdx.x;
    unsigned gen = 0;
    {   // init hidden
        int i = bid * 256 + tid;
        int u = i >> 5, b = i & 31;
        g_h[PIDX(u, b)] = hid[b * 1024 + u];
    }
    gridbar(gen);
    const int j0 = bid * 16;
    const int u0 = bid * 8;
    const float* Wh = g_whT + (size_t)bid * 32 * 2048;
    for (int t = 0; t < 512; t++) {
        // ---- backbone layer 0: act = concat(cfc_x_t, h) ----
        gemm_phase<16>(smem, g_w0T + (size_t)j0 * 2048,
                       g_cx + (size_t)t * 32768, g_h, warp, lane, tid);
#pragma unroll
        for (int q = 0; q < 2; q++) {
            int jj = warp * 2 + q;
            float s = bbb[j0 + jj];
#pragma unroll
            for (int w8 = 0; w8 < 8; w8++) s += sred[(w8 * 16 + jj) * 32 + lane];
            g_b1[PIDX(j0 + jj, lane)] = 1.7159f * tanhf(0.666f * s);
        }
        gridbar(gen);
        // ---- backbone layer 1 ----
        gemm_phase<16>(smem, g_w1T + (size_t)j0 * 2048,
                       g_b1, g_b1 + 32768, warp, lane, tid);
#pragma unroll
        for (int q = 0; q < 2; q++) {
            int jj = warp * 2 + q;
            float s = bbb[2048 + j0 + jj];
#pragma unroll
            for (int w8 = 0; w8 < 8; w8++) s += sred[(w8 * 16 + jj) * 32 + lane];
            g_b2[PIDX(j0 + jj, lane)] = 1.7159f * tanhf(0.666f * s);
        }
        gridbar(gen);
        // ---- heads (ff1|ff2|ta|tb for this block's 8 u-units) + fused gate ----
        gemm_phase<32>(smem, Wh, g_b2, g_b2 + 32768, warp, lane, tid);
#pragma unroll
        for (int q = 0; q < 4; q++) {
            int jj = warp * 4 + q;
            float s = 0.f;
#pragma unroll
            for (int w8 = 0; w8 < 8; w8++) s += sred[(w8 * 32 + jj) * 32 + lane];
            int grp = jj >> 3, u = u0 + (jj & 7);
            const float* bp = grp == 0 ? bf1 : grp == 1 ? bf2 : grp == 2 ? bta : btb;
            sH[jj * 32 + lane] = s + bp[u];
        }
        __syncthreads();
        {
            float v1 = tanhf(sH[warp * 32 + lane]);
            float v2 = tanhf(sH[(8 + warp) * 32 + lane]);
            float ta = sH[(16 + warp) * 32 + lane];
            float tb = sH[(24 + warp) * 32 + lane];
            float ts = tsp[lane * 512 + t];
            float ti = 1.f / (1.f + expf(-(ta * ts + tb)));
            float hn = v1 + ti * (v2 - v1);
            int p = PIDX(u0 + warp, lane);
            g_h[p] = hn;
            g_co[(size_t)t * 32768 + p] = hn;
        }
        gridbar(gen);
    }
}

// ---------------- h_final writeback ----------------
__global__ void k_hf(float* __restrict__ out) {
    int i = blockIdx.x * 256 + threadIdx.x;
    int u = i & 1023, b = i >> 10;
    out[i] = g_h[PIDX(u, b)];
}

// ---------------- host ----------------
extern "C" void kernel_launch(void* const* d_in, const int* in_sizes, int n_in,
                              void* d_out, int out_size) {
    const float* x    = (const float*)d_in[0];
    const float* tsp  = (const float*)d_in[1];
    const float* hid  = (const float*)d_in[2];
    const float* nw   = (const float*)d_in[3];
    const float* nb   = (const float*)d_in[4];
    const float* w_in = (const float*)d_in[5];
    const float* b_in = (const float*)d_in[6];
    const float* bbw  = (const float*)d_in[7];
    const float* bbb  = (const float*)d_in[8];
    const float* wf1  = (const float*)d_in[9];
    const float* bf1  = (const float*)d_in[10];
    const float* wf2  = (const float*)d_in[11];
    const float* bf2  = (const float*)d_in[12];
    const float* wta  = (const float*)d_in[13];
    const float* bta  = (const float*)d_in[14];
    const float* wtb  = (const float*)d_in[15];
    const float* btb  = (const float*)d_in[16];
    const float* w_out= (const float*)d_in[17];
    const float* b_out= (const float*)d_in[18];
    float* y  = (float*)d_out;
    float* hf = y + 16777216;

    static int s_attr_set = 0;
    if (!s_attr_set) {
        cudaFuncSetAttribute(k_scan, cudaFuncAttributeMaxDynamicSharedMemorySize, 167936);
        s_attr_set = 1;
    }

    dim3 tb(32, 8);
    k_init<<<1, 1>>>();
    k_trA<<<dim3(64, 64, 2), tb>>>(bbw);
    k_trB<<<dim3(32, 64, 6), tb>>>(w_in, w_out, wf1, wf2, wta, wtb);
    k_ln<<<512, 256>>>(x, nw, nb);
    k_gin<<<dim3(16, 128), 256>>>(b_in);
    k_scan<<<128, 256, 167936>>>(tsp, hid, bbb, bf1, bf2, bta, btb);
    k_gout<<<dim3(16, 128), 256>>>(b_out, x, y);
    k_hf<<<128, 256>>>(hf);
}

// round 5
// speedup vs baseline: 3.3271x; 1.6033x over previous
#include <cuda_runtime.h>
#include <cstdint>

typedef unsigned long long ull;

#define PIDX(k,b) (((((k)>>1))<<6) + (((b))<<1) + ((k)&1))

// ---------------- device scratch ----------------
__device__ __align__(16) float g_xn [512*1024*32]; // xn packed  [t][d2][b][2]
__device__ __align__(16) float g_cx [512*1024*32]; // cfc_x packed
__device__ __align__(16) float g_co [512*1024*32]; // cfc_out packed
__device__ __align__(16) float g_h  [1024*32];     // hidden packed
__device__ __align__(16) float g_b1 [2048*32];     // backbone L0 out packed
__device__ __align__(16) float g_b2 [2048*32];     // backbone L1 out packed
__device__ __align__(16) float g_winT [1024*1024]; // [j][k]
__device__ __align__(16) float g_w0T  [2048*2048];
__device__ __align__(16) float g_w1T  [2048*2048];
__device__ __align__(16) float g_whT  [4096*2048]; // interleaved heads rows
__device__ __align__(16) float g_woutT[1024*1024];
__device__ unsigned g_bar;

// ---------------- helpers ----------------
__device__ __forceinline__ ull f2fma(ull a, ull b, ull c) {
    ull d; asm("fma.rn.f32x2 %0,%1,%2,%3;" : "=l"(d) : "l"(a), "l"(b), "l"(c));
    return d;
}
__device__ __forceinline__ float2 u2f(ull v) {
    float2 f; asm("mov.b64 {%0,%1},%2;" : "=f"(f.x), "=f"(f.y) : "l"(v));
    return f;
}
__device__ __forceinline__ void cpa16(uint32_t s, const float* g) {
    asm volatile("cp.async.cg.shared.global [%0],[%1],16;" :: "r"(s), "l"(g));
}
__device__ __forceinline__ void cp_commit() { asm volatile("cp.async.commit_group;"); }

__device__ __forceinline__ void bar_arrive(unsigned& gen) {
    __syncthreads();
    gen++;
    if (threadIdx.x == 0) {
        __threadfence();
        atomicAdd(&g_bar, 1u);
    }
}
__device__ __forceinline__ void bar_wait(unsigned gen) {
    if (threadIdx.x == 0) {
        unsigned tgt = gen * gridDim.x;
        unsigned v;
        do {
            asm volatile("ld.acquire.gpu.u32 %0,[%1];" : "=r"(v) : "l"(&g_bar) : "memory");
        } while (v < tgt);
    }
    __syncthreads();
}

// ---------------- fused transposes (+ g_bar reset) ----------------
__global__ __launch_bounds__(256) void k_tr(const float* __restrict__ bbw,
                                            const float* __restrict__ win,
                                            const float* __restrict__ wout,
                                            const float* __restrict__ wf1,
                                            const float* __restrict__ wf2,
                                            const float* __restrict__ wta,
                                            const float* __restrict__ wtb) {
    __shared__ float tile[32][33];
    int z = blockIdx.z;
    int c0 = blockIdx.x * 32, r0 = blockIdx.y * 32;
    int x = threadIdx.x, y = threadIdx.y;
    if (z == 0 && blockIdx.x == 0 && blockIdx.y == 0 && threadIdx.x == 0 && threadIdx.y == 0)
        g_bar = 0u;
    if (z < 2) {
        const float* src = bbw + (size_t)z * 4194304;
        float* dst = z ? g_w1T : g_w0T;
#pragma unroll
        for (int i = 0; i < 32; i += 8)
            tile[y + i][x] = src[(size_t)(r0 + y + i) * 2048 + c0 + x];
        __syncthreads();
#pragma unroll
        for (int i = 0; i < 32; i += 8)
            dst[(size_t)(c0 + y + i) * 2048 + r0 + x] = tile[x][y + i];
    } else if (z < 4) {
        if (blockIdx.x >= 32 || blockIdx.y >= 32) return;
        const float* src = (z == 3) ? wout : win;
        float* dst = (z == 3) ? g_woutT : g_winT;
#pragma unroll
        for (int i = 0; i < 32; i += 8)
            tile[y + i][x] = src[(size_t)(r0 + y + i) * 1024 + c0 + x];
        __syncthreads();
#pragma unroll
        for (int i = 0; i < 32; i += 8)
            dst[(size_t)(c0 + y + i) * 1024 + r0 + x] = tile[x][y + i];
    } else {
        if (blockIdx.x >= 32) return;
        int h = z - 4;
        const float* src = h == 0 ? wf1 : h == 1 ? wf2 : h == 2 ? wta : wtb;
#pragma unroll
        for (int i = 0; i < 32; i += 8)
            tile[y + i][x] = src[(size_t)(r0 + y + i) * 1024 + c0 + x];
        __syncthreads();
#pragma unroll
        for (int i = 0; i < 32; i += 8) {
            int j = c0 + y + i;
            int f = ((j >> 3) << 5) + h * 8 + (j & 7);
            g_whT[(size_t)f * 2048 + r0 + x] = tile[x][y + i];
        }
    }
}

// ---------------- layernorm -> packed xn ----------------
__global__ __launch_bounds__(256) void k_ln(const float* __restrict__ x,
                                            const float* __restrict__ nw,
                                            const float* __restrict__ nb) {
    const int t = blockIdx.x;
    __shared__ float smu[32], srs[32];
    int warp = threadIdx.x >> 5, lane = threadIdx.x & 31;
    for (int b = warp; b < 32; b += 8) {
        const float* row = x + (size_t)b * 524288 + (size_t)t * 1024;
        float s = 0.f, s2 = 0.f;
        for (int d = lane; d < 1024; d += 32) { float v = row[d]; s += v; s2 += v * v; }
#pragma unroll
        for (int o = 16; o; o >>= 1) {
            s  += __shfl_xor_sync(0xffffffffu, s, o);
            s2 += __shfl_xor_sync(0xffffffffu, s2, o);
        }
        if (lane == 0) {
            float mu = s * (1.f / 1024.f);
            float var = s2 * (1.f / 1024.f) - mu * mu;
            smu[b] = mu; srs[b] = rsqrtf(var + 1e-5f);
        }
    }
    __syncthreads();
    float* dst = g_xn + (size_t)t * 32768;
    for (int b = warp; b < 32; b += 8) {
        const float* row = x + (size_t)b * 524288 + (size_t)t * 1024;
        float mu = smu[b], rs = srs[b];
        for (int d = lane; d < 1024; d += 32)
            dst[PIDX(d, b)] = (row[d] - mu) * rs * nw[d] + nb[d];
    }
}

// ---------------- input projection: cfc_x = xn @ w_inT + b_in ----------------
__global__ __launch_bounds__(256) void k_gin(const float* __restrict__ bias) {
    const int tid = threadIdx.x, warp = tid >> 5, lane = tid & 31;
    const int j0 = blockIdx.x * 64 + warp * 8;
    const int t0 = blockIdx.y * 4;
    ull acc[4][8];
#pragma unroll
    for (int tt = 0; tt < 4; tt++)
#pragma unroll
        for (int j = 0; j < 8; j++) acc[tt][j] = 0ull;
    const ull* xp = (const ull*)g_xn;
#pragma unroll 1
    for (int k4 = 0; k4 < 256; k4++) {
        ull a0[4], a1[4];
#pragma unroll
        for (int tt = 0; tt < 4; tt++) {
            const ull* ap = xp + (size_t)(t0 + tt) * 16384 + (size_t)(2 * k4) * 32;
            a0[tt] = ap[lane]; a1[tt] = ap[lane + 32];
        }
#pragma unroll
        for (int j = 0; j < 8; j++) {
            ulonglong2 wv = *(const ulonglong2*)(g_winT + (size_t)(j0 + j) * 1024 + 4 * k4);
#pragma unroll
            for (int tt = 0; tt < 4; tt++) {
                acc[tt][j] = f2fma(a0[tt], wv.x, acc[tt][j]);
                acc[tt][j] = f2fma(a1[tt], wv.y, acc[tt][j]);
            }
        }
    }
#pragma unroll
    for (int tt = 0; tt < 4; tt++)
#pragma unroll
        for (int j = 0; j < 8; j++) {
            float2 s = u2f(acc[tt][j]);
            g_cx[(size_t)(t0 + tt) * 32768 + PIDX(j0 + j, lane)] = s.x + s.y + bias[j0 + j];
        }
}

// ---------------- output projection + residual ----------------
__global__ __launch_bounds__(256) void k_gout(const float* __restrict__ bias,
                                              const float* __restrict__ x,
                                              float* __restrict__ y) {
    const int tid = threadIdx.x, warp = tid >> 5, lane = tid & 31;
    const int j0 = blockIdx.x * 64 + warp * 8;
    const int t0 = blockIdx.y * 4;
    ull acc[4][8];
#pragma unroll
    for (int tt = 0; tt < 4; tt++)
#pragma unroll
        for (int j = 0; j < 8; j++) acc[tt][j] = 0ull;
    const ull* cp = (const ull*)g_co;
#pragma unroll 1
    for (int k4 = 0; k4 < 256; k4++) {
        ull a0[4], a1[4];
#pragma unroll
        for (int tt = 0; tt < 4; tt++) {
            const ull* ap = cp + (size_t)(t0 + tt) * 16384 + (size_t)(2 * k4) * 32;
            a0[tt] = ap[lane]; a1[tt] = ap[lane + 32];
        }
#pragma unroll
        for (int j = 0; j < 8; j++) {
            ulonglong2 wv = *(const ulonglong2*)(g_woutT + (size_t)(j0 + j) * 1024 + 4 * k4);
#pragma unroll
            for (int tt = 0; tt < 4; tt++) {
                acc[tt][j] = f2fma(a0[tt], wv.x, acc[tt][j]);
                acc[tt][j] = f2fma(a1[tt], wv.y, acc[tt][j]);
            }
        }
    }
#pragma unroll
    for (int tt = 0; tt < 4; tt++)
#pragma unroll
        for (int j = 0; j < 8; j++) {
            int d = j0 + j;
            size_t oi = (size_t)lane * 524288 + (size_t)(t0 + tt) * 1024 + d;
            float2 s = u2f(acc[tt][j]);
            y[oi] = s.x + s.y + bias[d] + x[oi];
        }
}

// ---------------- scan smem layout (floats) ----------------
//  wb   : 3 x 8192  (weight tiles, ROWS x 256, ROWS<=32)
//  ab   : 3 x 8192  (act tiles, 256k x 32b)
//  sred : 8192      (8 warps x 32 rows x 32 lanes; also reused as sH)
#define SM_WB 0
#define SM_AB 24576
#define SM_SR 49152

template<int ROWS>
__device__ __forceinline__ void pfW(float* smem, int buf, const float* Wt, int tid) {
    uint32_t sw = (uint32_t)__cvta_generic_to_shared(smem + SM_WB + buf * 8192);
#pragma unroll
    for (int r = 0; r < ROWS / 4; r++) {
        int o = r * 256 + tid;
        int row = o >> 6, c = (o & 63) << 2;
        cpa16(sw + (uint32_t)(row * 256 + c) * 4u, Wt + (size_t)row * 2048 + c);
    }
}
__device__ __forceinline__ void pfA(float* smem, int buf, const float* At, int tid) {
    uint32_t sa = (uint32_t)__cvta_generic_to_shared(smem + SM_AB + buf * 8192);
#pragma unroll
    for (int r = 0; r < 8; r++) {
        int o = r * 256 + tid;
        cpa16(sa + (uint32_t)o * 16u, At + o * 4);
    }
}

// caller must have already committed W tiles 0 (buf0) and 1 (buf1)
template<int ROWS>
__device__ __forceinline__ void gemm_phase(
    float* smem, const float* Wbase, const float* actA, const float* actB,
    int warp, int lane, int tid)
{
    pfA(smem, 0, actA, tid);        cp_commit();
    pfA(smem, 1, actA + 8192, tid); cp_commit();
    ull acc[ROWS];
#pragma unroll
    for (int j = 0; j < ROWS; j++) acc[j] = 0ull;
    float* sred = smem + SM_SR;
#pragma unroll 1
    for (int kt = 0; kt < 8; kt++) {
        if (kt < 7) asm volatile("cp.async.wait_group 1;");
        else        asm volatile("cp.async.wait_group 0;");
        __syncthreads();
        if (kt < 6) {
            int n = kt + 2;
            const float* At = (n < 4) ? actA + n * 8192 : actB + (n - 4) * 8192;
            pfW<ROWS>(smem, n % 3, Wbase + n * 256, tid);
            pfA(smem, n % 3, At, tid);
            cp_commit();
        }
        const float* w = smem + SM_WB + (kt % 3) * 8192;
        const ull* au = (const ull*)(smem + SM_AB + (kt % 3) * 8192);
        const int k2lo = warp * 16;
#pragma unroll 2
        for (int k2 = 0; k2 < 16; k2 += 2) {
            ull a0 = au[(k2lo + k2) * 32 + lane];
            ull a1 = au[(k2lo + k2 + 1) * 32 + lane];
#pragma unroll
            for (int j = 0; j < ROWS; j++) {
                ulonglong2 wv = *(const ulonglong2*)(w + j * 256 + (k2lo + k2) * 2);
                acc[j] = f2fma(a0, wv.x, acc[j]);
                acc[j] = f2fma(a1, wv.y, acc[j]);
            }
        }
    }
    __syncthreads();
#pragma unroll
    for (int j = 0; j < ROWS; j++) {
        float2 p = u2f(acc[j]);
        sred[(warp * ROWS + j) * 32 + lane] = p.x + p.y;
    }
    __syncthreads();
}

// ---------------- persistent CfC scan ----------------
extern __shared__ float s_dyn[];

__global__ __launch_bounds__(256, 1) void k_scan(const float* __restrict__ tsp,
                                                 const float* __restrict__ hid,
                                                 const float* __restrict__ bbb,
                                                 const float* __restrict__ bf1,
                                                 const float* __restrict__ bf2,
                                                 const float* __restrict__ bta,
                                                 const float* __restrict__ btb) {
    float* smem = s_dyn;
    float* sred = smem + SM_SR;
    const int tid = threadIdx.x, warp = tid >> 5, lane = tid & 31, bid = blockIdx.x;
    unsigned gen = 0;
    const int j0 = bid * 16;
    const int u0 = bid * 8;
    const float* W0 = g_w0T + (size_t)j0 * 2048;
    const float* W1 = g_w1T + (size_t)j0 * 2048;
    const float* Wh = g_whT + (size_t)bid * 32 * 2048;
    {   // init hidden
        int i = bid * 256 + tid;
        int u = i >> 5, b = i & 31;
        g_h[PIDX(u, b)] = hid[b * 1024 + u];
    }
    bar_arrive(gen);
    // prefetch L0 W tiles 0,1 while waiting
    pfW<16>(smem, 0, W0, tid);       cp_commit();
    pfW<16>(smem, 1, W0 + 256, tid); cp_commit();
    bar_wait(gen);

    for (int t = 0; t < 512; t++) {
        // ---- backbone layer 0: act = concat(cfc_x_t, h) ----
        gemm_phase<16>(smem, W0, g_cx + (size_t)t * 32768, g_h, warp, lane, tid);
#pragma unroll
        for (int q = 0; q < 2; q++) {
            int jj = warp * 2 + q;
            float s = bbb[j0 + jj];
#pragma unroll
            for (int w8 = 0; w8 < 8; w8++) s += sred[(w8 * 16 + jj) * 32 + lane];
            g_b1[PIDX(j0 + jj, lane)] = 1.7159f * tanhf(0.666f * s);
        }
        bar_arrive(gen);
        pfW<16>(smem, 0, W1, tid);       cp_commit();
        pfW<16>(smem, 1, W1 + 256, tid); cp_commit();
        bar_wait(gen);
        // ---- backbone layer 1 ----
        gemm_phase<16>(smem, W1, g_b1, g_b1 + 32768, warp, lane, tid);
#pragma unroll
        for (int q = 0; q < 2; q++) {
            int jj = warp * 2 + q;
            float s = bbb[2048 + j0 + jj];
#pragma unroll
            for (int w8 = 0; w8 < 8; w8++) s += sred[(w8 * 16 + jj) * 32 + lane];
            g_b2[PIDX(j0 + jj, lane)] = 1.7159f * tanhf(0.666f * s);
        }
        bar_arrive(gen);
        pfW<32>(smem, 0, Wh, tid);       cp_commit();
        pfW<32>(smem, 1, Wh + 256, tid); cp_commit();
        bar_wait(gen);
        // ---- heads (ff1|ff2|ta|tb for this block's 8 u-units), block-local ----
        gemm_phase<32>(smem, Wh, g_b2, g_b2 + 32768, warp, lane, tid);
        float sval[4];
#pragma unroll
        for (int q = 0; q < 4; q++) {
            int jj = warp * 4 + q;
            float s = 0.f;
#pragma unroll
            for (int w8 = 0; w8 < 8; w8++) s += sred[(w8 * 32 + jj) * 32 + lane];
            int grp = jj >> 3, u = u0 + (jj & 7);
            const float* bp = grp == 0 ? bf1 : grp == 1 ? bf2 : grp == 2 ? bta : btb;
            sval[q] = s + bp[u];
        }
        __syncthreads();
#pragma unroll
        for (int q = 0; q < 4; q++) sred[(warp * 4 + q) * 32 + lane] = sval[q];
        __syncthreads();
        {   // fused CfC gate (this block's 8 u-units x 32 batches)
            float v1 = tanhf(sred[warp * 32 + lane]);
            float v2 = tanhf(sred[(8 + warp) * 32 + lane]);
            float ta = sred[(16 + warp) * 32 + lane];
            float tb = sred[(24 + warp) * 32 + lane];
            float ts = tsp[lane * 512 + t];
            float ti = 1.f / (1.f + expf(-(ta * ts + tb)));
            float hn = v1 + ti * (v2 - v1);
            int p = PIDX(u0 + warp, lane);
            g_h[p] = hn;
            g_co[(size_t)t * 32768 + p] = hn;
        }
        bar_arrive(gen);
        pfW<16>(smem, 0, W0, tid);       cp_commit();
        pfW<16>(smem, 1, W0 + 256, tid); cp_commit();
        bar_wait(gen);
    }
}

// ---------------- h_final writeback ----------------
__global__ void k_hf(float* __restrict__ out) {
    int i = blockIdx.x * 256 + threadIdx.x;
    int u = i & 1023, b = i >> 10;
    out[i] = g_h[PIDX(u, b)];
}

// ---------------- host ----------------
extern "C" void kernel_launch(void* const* d_in, const int* in_sizes, int n_in,
                              void* d_out, int out_size) {
    const float* x    = (const float*)d_in[0];
    const float* tsp  = (const float*)d_in[1];
    const float* hid  = (const float*)d_in[2];
    const float* nw   = (const float*)d_in[3];
    const float* nb   = (const float*)d_in[4];
    const float* w_in = (const float*)d_in[5];
    const float* b_in = (const float*)d_in[6];
    const float* bbw  = (const float*)d_in[7];
    const float* bbb  = (const float*)d_in[8];
    const float* wf1  = (const float*)d_in[9];
    const float* bf1  = (const float*)d_in[10];
    const float* wf2  = (const float*)d_in[11];
    const float* bf2  = (const float*)d_in[12];
    const float* wta  = (const float*)d_in[13];
    const float* bta  = (const float*)d_in[14];
    const float* wtb  = (const float*)d_in[15];
    const float* btb  = (const float*)d_in[16];
    const float* w_out= (const float*)d_in[17];
    const float* b_out= (const float*)d_in[18];
    float* y  = (float*)d_out;
    float* hf = y + 16777216;

    static int s_attr_set = 0;
    if (!s_attr_set) {
        cudaFuncSetAttribute(k_scan, cudaFuncAttributeMaxDynamicSharedMemorySize, 229376);
        s_attr_set = 1;
    }

    dim3 tb(32, 8);
    k_tr<<<dim3(64, 64, 8), tb>>>(bbw, w_in, w_out, wf1, wf2, wta, wtb);
    k_ln<<<512, 256>>>(x, nw, nb);
    k_gin<<<dim3(16, 128), 256>>>(b_in);
    k_scan<<<128, 256, 229376>>>(tsp, hid, bbb, bf1, bf2, bta, btb);
    k_gout<<<dim3(16, 128), 256>>>(b_out, x, y);
    k_hf<<<128, 256>>>(hf);
}